// round 17
// baseline (speedup 1.0000x reference)
#include <cuda_runtime.h>
#include <cuda_bf16.h>
#include <cstdint>

typedef unsigned long long ull;

#define BTOT 65536
#define TILES 13108   // ceil(65536/5)

__device__ float g_A[576];          // 4 x 12x12 premix matrices
__device__ float g_b4p[64];         // padded layer-4 bias
__device__ float g_W4p[128 * 64];   // padded layer-4 W
// packed W slabs: per (nc,kc): [hi NCH x 32 bf16 | lo ...], SW128
__device__ __align__(1024) uint8_t g_Wp[1245184];
#define WP_L1 0u
#define WP_L2 524288u
#define WP_L3 1048576u
#define WP_L4 1179648u

__device__ float g_h1[(size_t)BTOT * 12 * 512];
__device__ float g_h2[(size_t)BTOT * 12 * 256];
__device__ float g_h3[(size_t)BTOT * 12 * 128];

// ---------------------------------------------------------------------------
__global__ void prep(const float* __restrict__ adj,
                     const float* __restrict__ nv1,
                     const float* __restrict__ nv2,
                     const float* __restrict__ a1,
                     const float* __restrict__ a2,
                     const float* __restrict__ a3,
                     const float* __restrict__ a4,
                     const float* __restrict__ b4,
                     const float* __restrict__ W4)
{
    int t = blockIdx.x * blockDim.x + threadIdx.x;
    if (t < 128 * 64) {
        int k = t / 64, o = t % 64;
        g_W4p[t] = (o < 40) ? W4[k * 40 + o] : 0.f;
    }
    if (blockIdx.x == 0) {
        int n = threadIdx.x;
        if (n < 64) g_b4p[n] = (n < 40) ? b4[n] : 0.f;
        if (n < 12) {
            float r[12];
            float mx = -1e30f;
            for (int m = 0; m < 12; m++) {
                float s = 0.f;
                for (int k = 0; k < 10; k++)
                    s += nv1[n * 10 + k] * nv2[k * 12 + m];
                s = fmaxf(s, 0.f);
                r[m] = s;
                mx = fmaxf(mx, s);
            }
            float den = 0.f;
            for (int m = 0; m < 12; m++) { r[m] = expf(r[m] - mx); den += r[m]; }
            float inv = 1.f / den;
            for (int m = 0; m < 12; m++) {
                float av = adj[n * 12 + m] + r[m] * inv;
                g_A[0 * 144 + n * 12 + m] = a1[n * 12 + m] * av;
                g_A[1 * 144 + n * 12 + m] = a2[n * 12 + m] * av;
                g_A[2 * 144 + n * 12 + m] = a3[n * 12 + m] * av;
                g_A[3 * 144 + n * 12 + m] = a4[n * 12 + m] * av;
            }
        }
    }
}

// all four W packs; NCH=128 (L4: 64)
__global__ void pack_all(const float* __restrict__ W1,
                         const float* __restrict__ W2,
                         const float* __restrict__ W3)
{
    int idx = blockIdx.x * blockDim.x + threadIdx.x;
    const float* W;
    int K, O, NCH, rel;
    unsigned base;
    if (idx < 131072)      { W = W1;    K = 256; O = 512; NCH = 128; base = WP_L1; rel = idx; }
    else if (idx < 262144) { W = W2;    K = 512; O = 256; NCH = 128; base = WP_L2; rel = idx - 131072; }
    else if (idx < 294912) { W = W3;    K = 256; O = 128; NCH = 128; base = WP_L3; rel = idx - 262144; }
    else if (idx < 303104) { W = g_W4p; K = 128; O = 64;  NCH = 64;  base = WP_L4; rel = idx - 294912; }
    else return;
    int k = rel / O, o = rel % O;
    float w = W[rel];
    __nv_bfloat16 hi = __float2bfloat16(w);
    __nv_bfloat16 lo = __float2bfloat16(w - __bfloat162float(hi));
    int nc = o / NCH, ln = o % NCH, kc = k / 32, kk = k & 31;
    unsigned slab = base + (unsigned)(nc * (K / 32) + kc) * (unsigned)(NCH * 128);
    unsigned off = (unsigned)ln * 64u + (unsigned)kk * 2u;
    unsigned sw = off ^ ((off >> 3) & 0x70u);
    *(__nv_bfloat16*)(g_Wp + slab + sw) = hi;
    *(__nv_bfloat16*)(g_Wp + slab + (unsigned)(NCH * 64) + sw) = lo;
}

// ---------------------------------------------------------------------------
__device__ __forceinline__ uint32_t smem_u32(const void* p)
{
    uint32_t a;
    asm("{ .reg .u64 t; cvta.to.shared.u64 t, %1; cvt.u32.u64 %0, t; }"
        : "=r"(a) : "l"(p));
    return a;
}
__device__ __forceinline__ void f2fma(ull& d, ull a, ull b)
{
    asm("fma.rn.f32x2 %0, %1, %2, %0;" : "+l"(d) : "l"(a), "l"(b));
}
__device__ __forceinline__ float2 f2unp(ull v)
{
    float2 r; asm("mov.b64 {%0, %1}, %2;" : "=f"(r.x), "=f"(r.y) : "l"(v));
    return r;
}
__device__ __forceinline__ uint32_t bf2pack(float lo, float hi)
{
    uint32_t r;
    asm("cvt.rn.bf16x2.f32 %0, %1, %2;" : "=r"(r) : "f"(hi), "f"(lo));
    return r;
}
__device__ __forceinline__ void mwait(uint32_t mbar, uint32_t parity)
{
    asm volatile(
        "{\n\t.reg .pred P;\n\tWL_%=:\n\t"
        "mbarrier.try_wait.parity.shared.b64 P, [%0], %1;\n\t"
        "@!P bra WL_%=;\n\t}"
        :: "r"(mbar), "r"(parity) : "memory");
}
__device__ __forceinline__ void bulk_g2s(uint32_t dst, const void* src,
                                         uint32_t bytes, uint32_t mbar)
{
    asm volatile(
        "cp.async.bulk.shared::cta.global.mbarrier::complete_tx::bytes "
        "[%0], [%1], %2, [%3];"
        :: "r"(dst), "l"(src), "r"(bytes), "r"(mbar) : "memory");
}
__device__ __forceinline__ void ldsm4(uint32_t a, uint32_t* r)
{
    asm volatile("ldmatrix.sync.aligned.m8n8.x4.shared.b16 {%0,%1,%2,%3}, [%4];"
                 : "=r"(r[0]), "=r"(r[1]), "=r"(r[2]), "=r"(r[3]) : "r"(a));
}
#define MBAR_INIT(a, c) \
    asm volatile("mbarrier.init.shared.b64 [%0], %1;" :: "r"(a), "r"(c) : "memory")
#define MBAR_EXPECT(a, b) \
    asm volatile("mbarrier.arrive.expect_tx.shared.b64 _, [%0], %1;" \
                 :: "r"(a), "r"(b) : "memory")
#define MBAR_ARRIVE(a) \
    asm volatile("mbarrier.arrive.shared.b64 _, [%0];" :: "r"(a) : "memory")
#define STS32(a, v) \
    asm volatile("st.shared.b32 [%0], %1;" :: "r"(a), "r"(v) : "memory")
#define MMA(d, a, b) \
    asm volatile("mma.sync.aligned.m16n8k16.row.col.f32.bf16.bf16.f32 " \
                 "{%0,%1,%2,%3}, {%4,%5,%6,%7}, {%8,%9}, {%0,%1,%2,%3};" \
                 : "+f"((d)[0]), "+f"((d)[1]), "+f"((d)[2]), "+f"((d)[3]) \
                 : "r"((a)[0]), "r"((a)[1]), "r"((a)[2]), "r"((a)[3]), \
                   "r"((b)[0]), "r"((b)[1]))
#define BARC() asm volatile("bar.sync 1, 256;" ::: "memory")

// ---------------------------------------------------------------------------
// dst = relu( premix(A, src) @ W + b )
// MT=64 (5 batches/tile), 2 CTAs/SM. Premix streamed: per mainloop step,
// one 32-K source chunk is staged (LDG 2 ahead), premixed into a 2-slot A
// ring, then MMA'd. Redundant re-premix per n-pass when NNC>1.
// ---------------------------------------------------------------------------
template <int KK, int OO, int NCH, int ST, bool FINAL>
__global__ __launch_bounds__(288, 2) void gemm_layer(
    const float* __restrict__ src, float* __restrict__ dst,
    const float* __restrict__ bias, const uint8_t* __restrict__ wsrc, int aidx)
{
    constexpr int MT = 64;
    constexpr int NCK = KK / 32;
    constexpr int NNC = OO / NCH;
    constexpr int NSTEP = NNC * NCK;
    constexpr int WN = 4;
    constexpr int WTN = NCH / WN;
    constexpr int MI = 2;
    constexpr int NJ = WTN / 8;
    constexpr int NJ4 = NJ / 2;
    constexpr int ASLAB = MT * 128;        // 8 KB (hi 4K + lo 4K)
    constexpr int BSLAB = NCH * 128;
    constexpr int BPT = 5;
    constexpr int VR = 60;
    constexpr int STG = VR * 32;           // floats per stage slot

    extern __shared__ uint8_t smem[];
    __shared__ __align__(8) ull bars[2 * ST];
    __shared__ __align__(8) float2 Ash2[144];
    const uint32_t Ab = smem_u32(smem);                 // A ring: 2 x ASLAB
    const uint32_t Bb = Ab + 2 * ASLAB;                 // B ring: ST x BSLAB
    float* stage = (float*)(smem + 2 * ASLAB + ST * BSLAB);   // 2 x STG floats
    const uint32_t fb = smem_u32(&bars[0]);
    const uint32_t eb = smem_u32(&bars[ST]);
    const int tid = threadIdx.x, l = tid & 31, w = tid >> 5;
    const int tile = blockIdx.x;

    if (tid == 0) {
#pragma unroll
        for (int s = 0; s < ST; s++) {
            MBAR_INIT(fb + 8 * s, 1);
            MBAR_INIT(eb + 8 * s, 8);
        }
    }
    if (tid < 144) {
        float a = g_A[aidx + tid];
        Ash2[tid] = make_float2(a, a);
    }
    __syncthreads();

    // ---------------- producer warp (warp 8) --------------------------------
    if (w == 8) {
        if (l == 0) {
            int eph = 1;
#pragma unroll 1
            for (int s = 0; s < NSTEP; s++) {
                const int st = s % ST;
                mwait(eb + 8 * st, eph);
                if (st == ST - 1) eph ^= 1;
                MBAR_EXPECT(fb + 8 * st, BSLAB);
                bulk_g2s(Bb + st * BSLAB, wsrc + (size_t)s * BSLAB, BSLAB,
                         fb + 8 * st);
            }
        }
        return;
    }

    long remv = ((long)BTOT - (long)tile * BPT) * 12;
    const int vrows = (remv > VR) ? VR : (int)remv;
    const size_t rowbase = (size_t)tile * VR;

    // premix thread mapping: t<160 -> (b, kp, nh)
    const int pb = tid / 32, pkp = (tid % 32) >> 1, pnh = tid & 1;
    const bool pok = tid < 160;

    // LDG of source chunk kc -> regs (2 x float4 per thread)
    float4 pf[2];
    auto ldg_chunk = [&](int s_next) {
        const int kc = s_next % NCK;
#pragma unroll
        for (int j = 0; j < 2; j++) {
            int i = tid + j * 256;
            float4 v = make_float4(0.f, 0.f, 0.f, 0.f);
            if (i < VR * 8) {
                int row = i >> 3, q = i & 7;
                if (row < vrows)
                    v = __ldg((const float4*)(src + (rowbase + row) * KK
                                              + kc * 32 + q * 4));
            }
            pf[j] = v;
        }
    };
    auto store_stage = [&](int slot) {
        float* sp = stage + slot * STG;
#pragma unroll
        for (int j = 0; j < 2; j++) {
            int i = tid + j * 256;
            if (i < VR * 8) {
                int row = i >> 3, q = i & 7;
                *(float4*)(sp + row * 32 + q * 4) = pf[j];
            }
        }
    };
    auto premix = [&](int slot) {
        if (!pok) return;
        const float* sp = stage + slot * STG;
        const uint32_t abase = Ab + slot * ASLAB;
        ull vm[12];
#pragma unroll
        for (int m = 0; m < 12; m++)
            vm[m] = *(const ull*)(sp + (pb * 12 + m) * 32 + pkp * 2);
#pragma unroll
        for (int nn = 0; nn < 6; nn++) {
            const int n = pnh * 6 + nn;
            ull acc = 0ull;
#pragma unroll
            for (int m = 0; m < 12; m++)
                f2fma(acc, vm[m], *(const ull*)&Ash2[n * 12 + m]);
            float2 f = f2unp(acc);
            uint32_t h = bf2pack(f.x, f.y);
            float v0 = __uint_as_float(h << 16);
            float v1 = __uint_as_float(h & 0xffff0000u);
            uint32_t lo = bf2pack(f.x - v0, f.y - v1);
            uint32_t off = (uint32_t)(pb * 12 + n) * 64u + pkp * 4u;
            uint32_t sw = off ^ ((off >> 3) & 0x70u);
            STS32(abase + sw, h);
            STS32(abase + MT * 64 + sw, lo);
        }
    };

    // ldmatrix per-lane byte offsets
    const int wm = w / WN, wn = w % WN;
    uint32_t aoff[MI][2], boff[NJ4][2];
    {
        const int ar = wm * 32 + (l & 15);
        const int kh = l >> 4;
#pragma unroll
        for (int mi = 0; mi < MI; mi++)
#pragma unroll
            for (int k16 = 0; k16 < 2; k16++) {
                uint32_t off = (uint32_t)(ar + mi * 16) * 64u + k16 * 32u + kh * 16u;
                aoff[mi][k16] = off ^ ((off >> 3) & 0x70u);
            }
        const int br = wn * WTN + (l & 7) + 8 * (l >> 4);
        const int bk = (l >> 3) & 1;
#pragma unroll
        for (int j = 0; j < NJ4; j++)
#pragma unroll
            for (int k16 = 0; k16 < 2; k16++) {
                uint32_t off = (uint32_t)(br + j * 16) * 64u + k16 * 32u + bk * 16u;
                boff[j][k16] = off ^ ((off >> 3) & 0x70u);
            }
    }

    float acc[MI][NJ][4];
#pragma unroll
    for (int mi = 0; mi < MI; mi++)
#pragma unroll
        for (int nj = 0; nj < NJ; nj++)
#pragma unroll
            for (int q = 0; q < 4; q++) acc[mi][nj][q] = 0.f;

    // prologue: stage+premix chunk 0, prefetch chunk 1
    ldg_chunk(0);
    store_stage(0);
    BARC();
    ldg_chunk(1);
    premix(0);

    int fph = 0;
#pragma unroll 1
    for (int s = 0; s < NSTEP; s++) {
        const int st = s % ST;
        BARC();   // prev premix + prev MMA complete
        if (s + 1 < NSTEP) {
            store_stage((s + 1) & 1);
            BARC();
            if (s + 2 < NSTEP) ldg_chunk(s + 2);
            premix((s + 1) & 1);
        }
        mwait(fb + 8 * st, fph);
        if (st == ST - 1) fph ^= 1;
        const uint32_t asl = Ab + (s & 1) * ASLAB;
        const uint32_t bsl = Bb + st * BSLAB;
#pragma unroll
        for (int k16 = 0; k16 < 2; k16++) {
            uint32_t Ah[MI][4], Al[MI][4], Bh[NJ4][4], Bl[NJ4][4];
#pragma unroll
            for (int mi = 0; mi < MI; mi++) {
                ldsm4(asl + aoff[mi][k16], Ah[mi]);
                ldsm4(asl + MT * 64 + aoff[mi][k16], Al[mi]);
            }
#pragma unroll
            for (int j = 0; j < NJ4; j++) {
                ldsm4(bsl + boff[j][k16], Bh[j]);
                ldsm4(bsl + NCH * 64 + boff[j][k16], Bl[j]);
            }
            if (k16 == 1 && l == 0) MBAR_ARRIVE(eb + 8 * st);
#pragma unroll
            for (int mi = 0; mi < MI; mi++)
#pragma unroll
                for (int j = 0; j < NJ4; j++) {
                    MMA(acc[mi][2 * j], Ah[mi], &Bh[j][0]);
                    MMA(acc[mi][2 * j + 1], Ah[mi], &Bh[j][2]);
                    MMA(acc[mi][2 * j], Ah[mi], &Bl[j][0]);
                    MMA(acc[mi][2 * j + 1], Ah[mi], &Bl[j][2]);
                    MMA(acc[mi][2 * j], Al[mi], &Bh[j][0]);
                    MMA(acc[mi][2 * j + 1], Al[mi], &Bh[j][2]);
                }
        }
        if ((s % NCK) == NCK - 1) {
            const int nc = s / NCK;
            constexpr size_t OSTR = FINAL ? 40 : OO;
#pragma unroll
            for (int mi = 0; mi < MI; mi++)
#pragma unroll
                for (int nj = 0; nj < NJ; nj++) {
                    const int r0 = wm * 32 + mi * 16 + (l >> 2);
                    const int c0 = nc * NCH + wn * WTN + nj * 8 + 2 * (l & 3);
                    float2 bv = *(const float2*)(bias + c0);
                    float v0 = fmaxf(acc[mi][nj][0] + bv.x, 0.f);
                    float v1 = fmaxf(acc[mi][nj][1] + bv.y, 0.f);
                    float v2 = fmaxf(acc[mi][nj][2] + bv.x, 0.f);
                    float v3 = fmaxf(acc[mi][nj][3] + bv.y, 0.f);
                    const bool cok = (!FINAL) || (c0 < 40);
                    const size_t gr = rowbase + r0;
                    if (cok && r0 < vrows)
                        *(float2*)(dst + gr * OSTR + c0) = make_float2(v0, v1);
                    if (cok && r0 + 8 < vrows)
                        *(float2*)(dst + (gr + 8) * OSTR + c0) = make_float2(v2, v3);
#pragma unroll
                    for (int q = 0; q < 4; q++) acc[mi][nj][q] = 0.f;
                }
        }
    }
}

// ---------------------------------------------------------------------------
extern "C" void kernel_launch(void* const* d_in, const int* in_sizes, int n_in,
                              void* d_out, int out_size)
{
    const float* x    = (const float*)d_in[0];
    const float* adj  = (const float*)d_in[1];
    const float* nv1  = (const float*)d_in[2];
    const float* nv2  = (const float*)d_in[3];
    const float* W1   = (const float*)d_in[4];
    const float* att1 = (const float*)d_in[5];
    const float* b1   = (const float*)d_in[6];
    const float* W2   = (const float*)d_in[7];
    const float* att2 = (const float*)d_in[8];
    const float* b2   = (const float*)d_in[9];
    const float* W3   = (const float*)d_in[10];
    const float* att3 = (const float*)d_in[11];
    const float* b3   = (const float*)d_in[12];
    const float* W4   = (const float*)d_in[13];
    const float* att4 = (const float*)d_in[14];
    const float* b4   = (const float*)d_in[15];
    float* out = (float*)d_out;

    void *ph1, *ph2, *ph3, *pb4, *pwp;
    cudaGetSymbolAddress(&ph1, g_h1);
    cudaGetSymbolAddress(&ph2, g_h2);
    cudaGetSymbolAddress(&ph3, g_h3);
    cudaGetSymbolAddress(&pb4, g_b4p);
    cudaGetSymbolAddress(&pwp, g_Wp);

    prep<<<32, 256>>>(adj, nv1, nv2, att1, att2, att3, att4, b4, W4);
    pack_all<<<1184, 256>>>(W1, W2, W3);

    const uint8_t* wp = (const uint8_t*)pwp;
    // SMEM: A ring 16384 + B ring ST*BSLAB + stage 15360
    const int SM1 = 16384 + 4 * 16384 + 15360;   // 97280
    const int SM4 = 16384 + 4 * 8192 + 15360;    // 64512
    cudaFuncSetAttribute((gemm_layer<256, 512, 128, 4, false>),
                         cudaFuncAttributeMaxDynamicSharedMemorySize, SM1);
    cudaFuncSetAttribute((gemm_layer<512, 256, 128, 4, false>),
                         cudaFuncAttributeMaxDynamicSharedMemorySize, SM1);
    cudaFuncSetAttribute((gemm_layer<256, 128, 128, 4, false>),
                         cudaFuncAttributeMaxDynamicSharedMemorySize, SM1);
    cudaFuncSetAttribute((gemm_layer<128, 64, 64, 4, true>),
                         cudaFuncAttributeMaxDynamicSharedMemorySize, SM4);

    gemm_layer<256, 512, 128, 4, false><<<TILES, 288, SM1>>>(
        x, (float*)ph1, b1, wp + WP_L1, 0);
    gemm_layer<512, 256, 128, 4, false><<<TILES, 288, SM1>>>(
        (const float*)ph1, (float*)ph2, b2, wp + WP_L2, 144);
    gemm_layer<256, 128, 128, 4, false><<<TILES, 288, SM1>>>(
        (const float*)ph2, (float*)ph3, b3, wp + WP_L3, 288);
    gemm_layer<128, 64, 64, 4, true><<<TILES, 288, SM4>>>(
        (const float*)ph3, out, (float*)pb4, wp + WP_L4, 432);
}